// round 2
// baseline (speedup 1.0000x reference)
#include <cuda_runtime.h>
#include <math.h>

#define B_      2
#define T_      2048
#define DMODEL  2048
#define NH      16
#define NKV     4
#define DK      128
#define NREP    4
#define FSCALE  0.08838834764831845f   /* 1/sqrt(128) */

// ---------------- scratch (allocation-free: __device__ globals) ----------------
__device__ float g_Q[(size_t)B_ * T_ * NH  * DK];   // [B,T,H,DK]
__device__ float g_K[(size_t)B_ * T_ * NKV * DK];   // [B,T,KVH,DK]
__device__ float g_V[(size_t)B_ * T_ * NKV * DK];
__device__ float g_A[(size_t)B_ * T_ * NH  * DK];   // attention output
__device__ float g_freq[32];

// ---------------- SGEMM: C[M,N] = A[M,K] * W[N,K]^T (all row-major) ------------
#define GBM 128
#define GBN 128
#define GBK 16

__global__ __launch_bounds__(256) void sgemm_abt(
    const float* __restrict__ A, const float* __restrict__ W,
    float* __restrict__ C, int M, int N, int K)
{
    __shared__ float As[GBK][GBM + 4];
    __shared__ float Ws[GBK][GBN + 4];

    const int tid = threadIdx.x;
    const int tx = tid & 15;
    const int ty = tid >> 4;
    const int m0 = blockIdx.y * GBM;
    const int n0 = blockIdx.x * GBN;

    // each thread loads 2 float4 from A-tile and 2 from W-tile
    const int r0 = tid >> 2;          // 0..63
    const int kc = (tid & 3) << 2;    // 0,4,8,12

    const float* Ap = A + (size_t)m0 * K;
    const float* Wp = W + (size_t)n0 * K;

    float acc[8][8];
#pragma unroll
    for (int i = 0; i < 8; i++)
#pragma unroll
        for (int j = 0; j < 8; j++) acc[i][j] = 0.f;

    float4 a0 = *(const float4*)(Ap + (size_t)r0        * K + kc);
    float4 a1 = *(const float4*)(Ap + (size_t)(r0 + 64) * K + kc);
    float4 w0 = *(const float4*)(Wp + (size_t)r0        * K + kc);
    float4 w1 = *(const float4*)(Wp + (size_t)(r0 + 64) * K + kc);

    for (int kt = GBK; kt <= K; kt += GBK) {
        // store current tile (transposed) to smem
        As[kc + 0][r0] = a0.x; As[kc + 1][r0] = a0.y; As[kc + 2][r0] = a0.z; As[kc + 3][r0] = a0.w;
        As[kc + 0][r0 + 64] = a1.x; As[kc + 1][r0 + 64] = a1.y; As[kc + 2][r0 + 64] = a1.z; As[kc + 3][r0 + 64] = a1.w;
        Ws[kc + 0][r0] = w0.x; Ws[kc + 1][r0] = w0.y; Ws[kc + 2][r0] = w0.z; Ws[kc + 3][r0] = w0.w;
        Ws[kc + 0][r0 + 64] = w1.x; Ws[kc + 1][r0 + 64] = w1.y; Ws[kc + 2][r0 + 64] = w1.z; Ws[kc + 3][r0 + 64] = w1.w;
        __syncthreads();

        // prefetch next tile into registers (hidden under compute)
        if (kt < K) {
            a0 = *(const float4*)(Ap + (size_t)r0        * K + kt + kc);
            a1 = *(const float4*)(Ap + (size_t)(r0 + 64) * K + kt + kc);
            w0 = *(const float4*)(Wp + (size_t)r0        * K + kt + kc);
            w1 = *(const float4*)(Wp + (size_t)(r0 + 64) * K + kt + kc);
        }

#pragma unroll
        for (int k = 0; k < GBK; k++) {
            float4 x0 = *(const float4*)&As[k][ty * 8];
            float4 x1 = *(const float4*)&As[k][ty * 8 + 4];
            float4 y0 = *(const float4*)&Ws[k][tx * 8];
            float4 y1 = *(const float4*)&Ws[k][tx * 8 + 4];
            float av[8] = {x0.x, x0.y, x0.z, x0.w, x1.x, x1.y, x1.z, x1.w};
            float bv[8] = {y0.x, y0.y, y0.z, y0.w, y1.x, y1.y, y1.z, y1.w};
#pragma unroll
            for (int i = 0; i < 8; i++)
#pragma unroll
                for (int j = 0; j < 8; j++)
                    acc[i][j] += av[i] * bv[j];
        }
        __syncthreads();
    }

    float* Cp = C + (size_t)(m0 + ty * 8) * N + n0 + tx * 8;
#pragma unroll
    for (int i = 0; i < 8; i++) {
        float4 v0 = make_float4(acc[i][0], acc[i][1], acc[i][2], acc[i][3]);
        float4 v1 = make_float4(acc[i][4], acc[i][5], acc[i][6], acc[i][7]);
        *(float4*)(Cp + (size_t)i * N)     = v0;
        *(float4*)(Cp + (size_t)i * N + 4) = v1;
    }
}

// ---------------- RoPE ---------------------------------------------------------
__global__ void freq_init_kernel()
{
    int i = threadIdx.x;
    if (i < 32) g_freq[i] = (float)pow(1.0e-4, (double)i / 31.0);
}

// NOTE: the reference's _apply_rotary indexes cos/sin by the HEAD axis
// (x.shape[1] after transpose), broadcasting over time. So the rotation angle
// is head_index * freq[i], identical for every token. We replicate that.
// x layout: [B*T, nh, 128]; rotate pairs (i, i+64) for i<32 (freqs 32..63 zero)
__global__ void rope_kernel(float* __restrict__ x, int nh)
{
    int idx = blockIdx.x * blockDim.x + threadIdx.x;
    int total = B_ * T_ * nh * 32;
    if (idx >= total) return;
    int i  = idx & 31;
    int h  = (idx >> 5) % nh;
    int bt = idx / (32 * nh);

    float fr = g_freq[i];
    float th = (float)h * fr;        // head index, not time (matches reference)
    float c, sn;
    sincosf(th, &sn, &c);

    size_t base = ((size_t)bt * nh + h) * DK;
    float x1 = x[base + i];
    float x2 = x[base + 64 + i];
    x[base + i]      =  x1 * c + x2 * sn;
    x[base + 64 + i] = -x1 * sn + x2 * c;
}

// ---------------- Flash attention (fp32, online softmax) -----------------------
#define FBM 128
#define FBN 64

struct FlashSmem {
    float Qs[DK][FBM + 4];    // Q^T tile
    float Ks[DK][FBN + 4];    // K^T tile
    float Vs[FBN][DK];        // V tile (natural)
    float Ss[FBN][FBM + 4];   // S^T / P^T tile
    float m_sm[FBM];
    float l_sm[FBM];
    float al_sm[FBM];
};

__global__ __launch_bounds__(256, 1) void flash_kernel(
    const float* __restrict__ Q, const float* __restrict__ Kp,
    const float* __restrict__ Vp, float* __restrict__ O)
{
    extern __shared__ char smem_raw[];
    FlashSmem& s = *reinterpret_cast<FlashSmem*>(smem_raw);

    const int tid = threadIdx.x;
    const int tx = tid & 15;       // n / d-col group
    const int ty = tid >> 4;       // m-row group
    const int qt = gridDim.x - 1 - blockIdx.x;   // big tiles first (load balance)
    const int bh = blockIdx.y;
    const int b  = bh >> 4;
    const int h  = bh & 15;
    const int kvh = h >> 2;
    const int q0 = qt * FBM;

    const int qstride = NH * DK;   // 2048
    const int kstride = NKV * DK;  // 512
    const float* Qb = Q  + ((size_t)(b * T_) * NH  + h)   * DK;
    const float* Kb = Kp + ((size_t)(b * T_) * NKV + kvh) * DK;
    const float* Vb = Vp + ((size_t)(b * T_) * NKV + kvh) * DK;

    // load Q tile transposed
    for (int f = tid; f < FBM * 32; f += 256) {
        int r = f >> 5, dc = (f & 31) << 2;
        float4 v = *(const float4*)(Qb + (size_t)(q0 + r) * qstride + dc);
        s.Qs[dc + 0][r] = v.x; s.Qs[dc + 1][r] = v.y;
        s.Qs[dc + 2][r] = v.z; s.Qs[dc + 3][r] = v.w;
    }
    if (tid < FBM) { s.m_sm[tid] = -1e30f; s.l_sm[tid] = 0.f; }

    float accO[8][8];
#pragma unroll
    for (int i = 0; i < 8; i++)
#pragma unroll
        for (int j = 0; j < 8; j++) accO[i][j] = 0.f;

    const int njt = 2 * (qt + 1);
    __syncthreads();

    for (int jt = 0; jt < njt; jt++) {
        const int j0 = jt * FBN;

        // load K tile transposed, V tile natural
        for (int f = tid; f < FBN * 32; f += 256) {
            int r = f >> 5, dc = (f & 31) << 2;
            float4 v = *(const float4*)(Kb + (size_t)(j0 + r) * kstride + dc);
            s.Ks[dc + 0][r] = v.x; s.Ks[dc + 1][r] = v.y;
            s.Ks[dc + 2][r] = v.z; s.Ks[dc + 3][r] = v.w;
        }
        for (int f = tid; f < FBN * 32; f += 256) {
            int r = f >> 5, dc = (f & 31) << 2;
            *(float4*)&s.Vs[r][dc] =
                *(const float4*)(Vb + (size_t)(j0 + r) * kstride + dc);
        }
        __syncthreads();

        // GEMM1: S = Q * K^T   (thread tile 8m x 4n)
        float accS[8][4];
#pragma unroll
        for (int i = 0; i < 8; i++)
#pragma unroll
            for (int j = 0; j < 4; j++) accS[i][j] = 0.f;

#pragma unroll 4
        for (int d = 0; d < DK; d++) {
            float4 x0 = *(const float4*)&s.Qs[d][ty * 8];
            float4 x1 = *(const float4*)&s.Qs[d][ty * 8 + 4];
            float4 y  = *(const float4*)&s.Ks[d][tx * 4];
            float av[8] = {x0.x, x0.y, x0.z, x0.w, x1.x, x1.y, x1.z, x1.w};
            float bv[4] = {y.x, y.y, y.z, y.w};
#pragma unroll
            for (int i = 0; i < 8; i++)
#pragma unroll
                for (int j = 0; j < 4; j++)
                    accS[i][j] += av[i] * bv[j];
        }

        // scale + causal mask, write S^T to smem
        const bool partial = (j0 >= q0);
#pragma unroll
        for (int i = 0; i < 8; i++) {
            int gi = q0 + ty * 8 + i;
#pragma unroll
            for (int j = 0; j < 4; j++) {
                float v = accS[i][j] * FSCALE;
                if (partial && (j0 + tx * 4 + j > gi)) v = -1e30f;
                s.Ss[tx * 4 + j][ty * 8 + i] = v;
            }
        }
        __syncthreads();

        // online softmax: one thread per query row
        if (tid < FBM) {
            const int m = tid;
            float mo = s.m_sm[m];
            float mx = mo;
#pragma unroll 8
            for (int j = 0; j < FBN; j++) mx = fmaxf(mx, s.Ss[j][m]);
            float alpha = __expf(mo - mx);
            float sum = 0.f;
#pragma unroll 8
            for (int j = 0; j < FBN; j++) {
                float p = __expf(s.Ss[j][m] - mx);
                s.Ss[j][m] = p;
                sum += p;
            }
            s.al_sm[m] = alpha;
            s.m_sm[m]  = mx;
            s.l_sm[m]  = s.l_sm[m] * alpha + sum;
        }
        __syncthreads();

        // rescale O, then GEMM2: O += P * V   (thread tile 8m x 8d)
        float alr[8];
#pragma unroll
        for (int i = 0; i < 8; i++) alr[i] = s.al_sm[ty * 8 + i];
#pragma unroll
        for (int i = 0; i < 8; i++)
#pragma unroll
            for (int jd = 0; jd < 8; jd++) accO[i][jd] *= alr[i];

#pragma unroll 2
        for (int j = 0; j < FBN; j++) {
            float4 p0 = *(const float4*)&s.Ss[j][ty * 8];
            float4 p1 = *(const float4*)&s.Ss[j][ty * 8 + 4];
            float4 v0 = *(const float4*)&s.Vs[j][tx * 8];
            float4 v1 = *(const float4*)&s.Vs[j][tx * 8 + 4];
            float pv[8] = {p0.x, p0.y, p0.z, p0.w, p1.x, p1.y, p1.z, p1.w};
            float vv[8] = {v0.x, v0.y, v0.z, v0.w, v1.x, v1.y, v1.z, v1.w};
#pragma unroll
            for (int i = 0; i < 8; i++)
#pragma unroll
                for (int jd = 0; jd < 8; jd++)
                    accO[i][jd] += pv[i] * vv[jd];
        }
        __syncthreads();
    }

    // epilogue: normalize and store
    float linv[8];
#pragma unroll
    for (int i = 0; i < 8; i++) linv[i] = 1.f / s.l_sm[ty * 8 + i];
    float* Ob = O + ((size_t)(b * T_) * NH + h) * DK;
#pragma unroll
    for (int i = 0; i < 8; i++) {
        float4 o0 = make_float4(accO[i][0] * linv[i], accO[i][1] * linv[i],
                                accO[i][2] * linv[i], accO[i][3] * linv[i]);
        float4 o1 = make_float4(accO[i][4] * linv[i], accO[i][5] * linv[i],
                                accO[i][6] * linv[i], accO[i][7] * linv[i]);
        float* dst = Ob + (size_t)(q0 + ty * 8 + i) * qstride + tx * 8;
        *(float4*)(dst)     = o0;
        *(float4*)(dst + 4) = o1;
    }
}

// ---------------- launch --------------------------------------------------------
extern "C" void kernel_launch(void* const* d_in, const int* in_sizes, int n_in,
                              void* d_out, int out_size)
{
    const float* x  = (const float*)d_in[0];
    const float* wq = (const float*)d_in[1];
    const float* wk = (const float*)d_in[2];
    const float* wv = (const float*)d_in[3];
    const float* wo = (const float*)d_in[4];
    float* out = (float*)d_out;

    float *Qd, *Kd, *Vd, *Ad;
    cudaGetSymbolAddress((void**)&Qd, g_Q);
    cudaGetSymbolAddress((void**)&Kd, g_K);
    cudaGetSymbolAddress((void**)&Vd, g_V);
    cudaGetSymbolAddress((void**)&Ad, g_A);

    const int M = B_ * T_;  // 4096

    freq_init_kernel<<<1, 32>>>();

    sgemm_abt<<<dim3(DMODEL / GBN, M / GBM), 256>>>(x, wq, Qd, M, DMODEL, DMODEL);
    sgemm_abt<<<dim3((NKV * DK) / GBN, M / GBM), 256>>>(x, wk, Kd, M, NKV * DK, DMODEL);
    sgemm_abt<<<dim3((NKV * DK) / GBN, M / GBM), 256>>>(x, wv, Vd, M, NKV * DK, DMODEL);

    rope_kernel<<<(B_ * T_ * NH * 32 + 255) / 256, 256>>>(Qd, NH);
    rope_kernel<<<(B_ * T_ * NKV * 32 + 255) / 256, 256>>>(Kd, NKV);

    const int fsm = (int)sizeof(FlashSmem);
    cudaFuncSetAttribute(flash_kernel,
                         cudaFuncAttributeMaxDynamicSharedMemorySize, fsm);
    flash_kernel<<<dim3(T_ / FBM, B_ * NH), 256, fsm>>>(Qd, Kd, Vd, Ad);

    sgemm_abt<<<dim3(DMODEL / GBN, M / GBM), 256>>>(Ad, wo, out, M, DMODEL, DMODEL);
}

// round 5
// speedup vs baseline: 1.4504x; 1.4504x over previous
#include <cuda_runtime.h>
#include <cuda_bf16.h>
#include <math.h>
#include <stdint.h>

#define B_      2
#define T_      2048
#define DMODEL  2048
#define NH      16
#define NKV     4
#define DK      128
#define FSCALE  0.08838834764831845f   /* 1/sqrt(128) */

// ---------------- scratch (allocation-free: __device__ globals) ----------------
__device__ float g_Q[(size_t)B_ * T_ * NH  * DK];   // [B*T, 2048]
__device__ float g_K[(size_t)B_ * T_ * NKV * DK];   // [B*T, 512]
__device__ float g_V[(size_t)B_ * T_ * NKV * DK];
__device__ float g_A[(size_t)B_ * T_ * NH  * DK];   // attention output
__device__ float g_freq[32];

// bf16 hi/lo splits
__device__ __nv_bfloat16 g_xhi[(size_t)4096 * 2048], g_xlo[(size_t)4096 * 2048];
__device__ __nv_bfloat16 g_ahi[(size_t)4096 * 2048], g_alo[(size_t)4096 * 2048];
__device__ __nv_bfloat16 g_wqhi[(size_t)2048 * 2048], g_wqlo[(size_t)2048 * 2048];
__device__ __nv_bfloat16 g_wkhi[(size_t)512  * 2048], g_wklo[(size_t)512  * 2048];
__device__ __nv_bfloat16 g_wvhi[(size_t)512  * 2048], g_wvlo[(size_t)512  * 2048];
__device__ __nv_bfloat16 g_wohi[(size_t)2048 * 2048], g_wolo[(size_t)2048 * 2048];

// ---------------- helpers -------------------------------------------------------
__device__ __forceinline__ uint32_t smem_u32(const void* p) {
    uint32_t a;
    asm("{ .reg .u64 t; cvta.to.shared.u64 t, %1; cvt.u32.u64 %0, t; }"
        : "=r"(a) : "l"(p));
    return a;
}
#define SWZ(x) ((x) ^ (((x) >> 3) & 0x70))

__device__ __forceinline__ void cpa16(uint32_t d, const void* s) {
    asm volatile("cp.async.cg.shared.global [%0], [%1], 16;" :: "r"(d), "l"(s));
}
__device__ __forceinline__ void cpa_commit() {
    asm volatile("cp.async.commit_group;" ::: "memory");
}
template <int N> __device__ __forceinline__ void cpa_wait() {
    asm volatile("cp.async.wait_group %0;" :: "n"(N) : "memory");
}

__device__ __forceinline__ void ldsm_x4(uint32_t* r, uint32_t a) {
    asm volatile("ldmatrix.sync.aligned.m8n8.x4.shared.b16 {%0,%1,%2,%3}, [%4];"
                 : "=r"(r[0]), "=r"(r[1]), "=r"(r[2]), "=r"(r[3]) : "r"(a));
}
__device__ __forceinline__ void ldsm_x2(uint32_t* r, uint32_t a) {
    asm volatile("ldmatrix.sync.aligned.m8n8.x2.shared.b16 {%0,%1}, [%2];"
                 : "=r"(r[0]), "=r"(r[1]) : "r"(a));
}
__device__ __forceinline__ void mma16816(float* c, const uint32_t* a, const uint32_t* b) {
    asm volatile(
        "mma.sync.aligned.m16n8k16.row.col.f32.bf16.bf16.f32 "
        "{%0,%1,%2,%3}, {%4,%5,%6,%7}, {%8,%9}, {%0,%1,%2,%3};"
        : "+f"(c[0]), "+f"(c[1]), "+f"(c[2]), "+f"(c[3])
        : "r"(a[0]), "r"(a[1]), "r"(a[2]), "r"(a[3]), "r"(b[0]), "r"(b[1]));
}

// ---------------- fp32 -> bf16 hi/lo split --------------------------------------
__global__ void cvt_split(const float* __restrict__ s,
                          __nv_bfloat16* __restrict__ hi,
                          __nv_bfloat16* __restrict__ lo, int n)
{
    int i = (blockIdx.x * blockDim.x + threadIdx.x) * 4;
    if (i >= n) return;
    float4 v = *(const float4*)(s + i);
    __nv_bfloat16 h0 = __float2bfloat16(v.x);
    __nv_bfloat16 h1 = __float2bfloat16(v.y);
    __nv_bfloat16 h2 = __float2bfloat16(v.z);
    __nv_bfloat16 h3 = __float2bfloat16(v.w);
    __nv_bfloat16 l0 = __float2bfloat16(v.x - __bfloat162float(h0));
    __nv_bfloat16 l1 = __float2bfloat16(v.y - __bfloat162float(h1));
    __nv_bfloat16 l2 = __float2bfloat16(v.z - __bfloat162float(h2));
    __nv_bfloat16 l3 = __float2bfloat16(v.w - __bfloat162float(h3));
    __nv_bfloat162* hp = (__nv_bfloat162*)(hi + i);
    __nv_bfloat162* lp = (__nv_bfloat162*)(lo + i);
    hp[0] = __nv_bfloat162(h0, h1); hp[1] = __nv_bfloat162(h2, h3);
    lp[0] = __nv_bfloat162(l0, l1); lp[1] = __nv_bfloat162(l2, l3);
}

// ---------------- HMMA bf16x3 GEMM: C[M,N] = (Ahi+Alo)(Whi+Wlo)^T ---------------
// 3 passes over K: (Ahi,Whi), (Alo,Whi), (Ahi,Wlo), fp32 accumulators in regs.
#define TKE 64                      // K elems per stage tile
#define STAGES 3
#define TILE_BYTES 16384            // 128 rows x 128 B
#define STAGE_BYTES (2 * TILE_BYTES)
#define GEMM_SMEM (STAGES * STAGE_BYTES)

__global__ __launch_bounds__(256, 1) void gemm_bf16x3(
    const __nv_bfloat16* __restrict__ Ahi, const __nv_bfloat16* __restrict__ Alo,
    const __nv_bfloat16* __restrict__ Whi, const __nv_bfloat16* __restrict__ Wlo,
    float* __restrict__ C, int N, int K)
{
    extern __shared__ char sm[];
    const uint32_t sb = smem_u32(sm);
    const int tid  = threadIdx.x;
    const int lane = tid & 31;
    const int wid  = tid >> 5;
    const int wm   = wid >> 2;       // 0..1 (64-row block)
    const int wn   = wid & 3;        // 0..3 (32-col block)
    const int m0 = blockIdx.y * 128, n0 = blockIdx.x * 128;

    const int nk = K / TKE;          // 32
    const int nIter = 3 * nk;        // 96

    // ldmatrix per-lane source rows (within tile, bytes)
    const int rA = lane & 15;
    const int kA2 = ((lane >> 4) & 1) * 16;       // bytes (8 elems)
    const int rB = lane & 7;
    const int kB2 = ((lane >> 3) & 1) * 16;
    uint32_t aRow[4], bRow[4];
#pragma unroll
    for (int mi = 0; mi < 4; mi++)
        aRow[mi] = (uint32_t)((wm * 64 + mi * 16 + rA) * 128 + kA2);
#pragma unroll
    for (int ni = 0; ni < 4; ni++)
        bRow[ni] = (uint32_t)((wn * 32 + ni * 8 + rB) * 128 + kB2);

    // cp.async geometry: 4 chunks of 16B per tile per thread
    uint32_t dstoff[4];
    int rowc[4], colc[4];
#pragma unroll
    for (int q = 0; q < 4; q++) {
        int ci = q * 256 + tid;
        int r = ci >> 3, c = ci & 7;
        rowc[q] = r; colc[q] = c;
        dstoff[q] = SWZ((uint32_t)(r * 128 + c * 16));
    }

    auto issue_loads = [&](int j) {
        int s = j % STAGES;
        int term = j / nk;
        int kt = (j % nk) * TKE;
        const __nv_bfloat16* Ab = (term == 1) ? Alo : Ahi;
        const __nv_bfloat16* Wb = (term == 2) ? Wlo : Whi;
        const char* Ap = (const char*)(Ab + (size_t)m0 * K + kt);
        const char* Wp = (const char*)(Wb + (size_t)n0 * K + kt);
        uint32_t as = sb + s * STAGE_BYTES;
        uint32_t ws = as + TILE_BYTES;
#pragma unroll
        for (int q = 0; q < 4; q++) {
            cpa16(as + dstoff[q], Ap + (size_t)rowc[q] * K * 2 + colc[q] * 16);
            cpa16(ws + dstoff[q], Wp + (size_t)rowc[q] * K * 2 + colc[q] * 16);
        }
        cpa_commit();
    };

    float acc[4][4][4];
#pragma unroll
    for (int mi = 0; mi < 4; mi++)
#pragma unroll
        for (int ni = 0; ni < 4; ni++)
#pragma unroll
            for (int q = 0; q < 4; q++) acc[mi][ni][q] = 0.f;

    issue_loads(0); issue_loads(1); issue_loads(2);

    for (int j = 0; j < nIter; j++) {
        const int s = j % STAGES;
        if (j < nIter - 2)       cpa_wait<2>();
        else if (j == nIter - 2) cpa_wait<1>();
        else                     cpa_wait<0>();
        __syncthreads();

        uint32_t as = sb + s * STAGE_BYTES;
        uint32_t ws = as + TILE_BYTES;
#pragma unroll
        for (int ks = 0; ks < 4; ks++) {
            uint32_t af[4][4], bf[4][2];
#pragma unroll
            for (int mi = 0; mi < 4; mi++)
                ldsm_x4(af[mi], as + SWZ(aRow[mi] + (uint32_t)ks * 32));
#pragma unroll
            for (int ni = 0; ni < 4; ni++)
                ldsm_x2(bf[ni], ws + SWZ(bRow[ni] + (uint32_t)ks * 32));
#pragma unroll
            for (int mi = 0; mi < 4; mi++)
#pragma unroll
                for (int ni = 0; ni < 4; ni++)
                    mma16816(acc[mi][ni], af[mi], bf[ni]);
        }
        __syncthreads();

        int jn = j + STAGES;
        if (jn < nIter) issue_loads(jn);
    }

    // epilogue: c0,c1 -> row r; c2,c3 -> row r+8; cols 2*(lane%4)+{0,1}
    const int rr = lane >> 2;
    const int cc = (lane & 3) * 2;
#pragma unroll
    for (int mi = 0; mi < 4; mi++) {
        int row = m0 + wm * 64 + mi * 16 + rr;
#pragma unroll
        for (int ni = 0; ni < 4; ni++) {
            int col = n0 + wn * 32 + ni * 8 + cc;
            float2 v0 = make_float2(acc[mi][ni][0], acc[mi][ni][1]);
            float2 v1 = make_float2(acc[mi][ni][2], acc[mi][ni][3]);
            *(float2*)(C + (size_t)row * N + col)       = v0;
            *(float2*)(C + (size_t)(row + 8) * N + col) = v1;
        }
    }
}

// ---------------- RoPE (head-indexed, matching reference) -----------------------
__global__ void freq_init_kernel()
{
    int i = threadIdx.x;
    if (i < 32) g_freq[i] = (float)pow(1.0e-4, (double)i / 31.0);
}

__global__ void rope_kernel(float* __restrict__ x, int nh)
{
    int idx = blockIdx.x * blockDim.x + threadIdx.x;
    int total = B_ * T_ * nh * 32;
    if (idx >= total) return;
    int i  = idx & 31;
    int h  = (idx >> 5) % nh;
    int bt = idx / (32 * nh);

    float fr = g_freq[i];
    float th = (float)h * fr;        // head index, not time (matches reference)
    float c, sn;
    sincosf(th, &sn, &c);

    size_t base = ((size_t)bt * nh + h) * DK;
    float x1 = x[base + i];
    float x2 = x[base + 64 + i];
    x[base + i]      =  x1 * c + x2 * sn;
    x[base + 64 + i] = -x1 * sn + x2 * c;
}

// ---------------- Flash attention (fp32, online softmax) -----------------------
#define FBM 128
#define FBN 64

struct FlashSmem {
    float Qs[DK][FBM + 4];
    float Ks[DK][FBN + 4];
    float Vs[FBN][DK];
    float Ss[FBN][FBM + 4];
    float m_sm[FBM];
    float l_sm[FBM];
    float al_sm[FBM];
};

__global__ __launch_bounds__(256, 1) void flash_kernel(
    const float* __restrict__ Q, const float* __restrict__ Kp,
    const float* __restrict__ Vp, float* __restrict__ O)
{
    extern __shared__ char smem_raw[];
    FlashSmem& s = *reinterpret_cast<FlashSmem*>(smem_raw);

    const int tid = threadIdx.x;
    const int tx = tid & 15;
    const int ty = tid >> 4;
    const int qt = gridDim.x - 1 - blockIdx.x;
    const int bh = blockIdx.y;
    const int b  = bh >> 4;
    const int h  = bh & 15;
    const int kvh = h >> 2;
    const int q0 = qt * FBM;

    const int qstride = NH * DK;
    const int kstride = NKV * DK;
    const float* Qb = Q  + ((size_t)(b * T_) * NH  + h)   * DK;
    const float* Kb = Kp + ((size_t)(b * T_) * NKV + kvh) * DK;
    const float* Vb = Vp + ((size_t)(b * T_) * NKV + kvh) * DK;

    for (int f = tid; f < FBM * 32; f += 256) {
        int r = f >> 5, dc = (f & 31) << 2;
        float4 v = *(const float4*)(Qb + (size_t)(q0 + r) * qstride + dc);
        s.Qs[dc + 0][r] = v.x; s.Qs[dc + 1][r] = v.y;
        s.Qs[dc + 2][r] = v.z; s.Qs[dc + 3][r] = v.w;
    }
    if (tid < FBM) { s.m_sm[tid] = -1e30f; s.l_sm[tid] = 0.f; }

    float accO[8][8];
#pragma unroll
    for (int i = 0; i < 8; i++)
#pragma unroll
        for (int j = 0; j < 8; j++) accO[i][j] = 0.f;

    const int njt = 2 * (qt + 1);
    __syncthreads();

    for (int jt = 0; jt < njt; jt++) {
        const int j0 = jt * FBN;

        for (int f = tid; f < FBN * 32; f += 256) {
            int r = f >> 5, dc = (f & 31) << 2;
            float4 v = *(const float4*)(Kb + (size_t)(j0 + r) * kstride + dc);
            s.Ks[dc + 0][r] = v.x; s.Ks[dc + 1][r] = v.y;
            s.Ks[dc + 2][r] = v.z; s.Ks[dc + 3][r] = v.w;
        }
        for (int f = tid; f < FBN * 32; f += 256) {
            int r = f >> 5, dc = (f & 31) << 2;
            *(float4*)&s.Vs[r][dc] =
                *(const float4*)(Vb + (size_t)(j0 + r) * kstride + dc);
        }
        __syncthreads();

        float accS[8][4];
#pragma unroll
        for (int i = 0; i < 8; i++)
#pragma unroll
            for (int j = 0; j < 4; j++) accS[i][j] = 0.f;

#pragma unroll 4
        for (int d = 0; d < DK; d++) {
            float4 x0 = *(const float4*)&s.Qs[d][ty * 8];
            float4 x1 = *(const float4*)&s.Qs[d][ty * 8 + 4];
            float4 y  = *(const float4*)&s.Ks[d][tx * 4];
            float av[8] = {x0.x, x0.y, x0.z, x0.w, x1.x, x1.y, x1.z, x1.w};
            float bv[4] = {y.x, y.y, y.z, y.w};
#pragma unroll
            for (int i = 0; i < 8; i++)
#pragma unroll
                for (int j = 0; j < 4; j++)
                    accS[i][j] += av[i] * bv[j];
        }

        const bool partial = (j0 >= q0);
#pragma unroll
        for (int i = 0; i < 8; i++) {
            int gi = q0 + ty * 8 + i;
#pragma unroll
            for (int j = 0; j < 4; j++) {
                float v = accS[i][j] * FSCALE;
                if (partial && (j0 + tx * 4 + j > gi)) v = -1e30f;
                s.Ss[tx * 4 + j][ty * 8 + i] = v;
            }
        }
        __syncthreads();

        if (tid < FBM) {
            const int m = tid;
            float mo = s.m_sm[m];
            float mx = mo;
#pragma unroll 8
            for (int j = 0; j < FBN; j++) mx = fmaxf(mx, s.Ss[j][m]);
            float alpha = __expf(mo - mx);
            float sum = 0.f;
#pragma unroll 8
            for (int j = 0; j < FBN; j++) {
                float p = __expf(s.Ss[j][m] - mx);
                s.Ss[j][m] = p;
                sum += p;
            }
            s.al_sm[m] = alpha;
            s.m_sm[m]  = mx;
            s.l_sm[m]  = s.l_sm[m] * alpha + sum;
        }
        __syncthreads();

        float alr[8];
#pragma unroll
        for (int i = 0; i < 8; i++) alr[i] = s.al_sm[ty * 8 + i];
#pragma unroll
        for (int i = 0; i < 8; i++)
#pragma unroll
            for (int jd = 0; jd < 8; jd++) accO[i][jd] *= alr[i];

#pragma unroll 2
        for (int j = 0; j < FBN; j++) {
            float4 p0 = *(const float4*)&s.Ss[j][ty * 8];
            float4 p1 = *(const float4*)&s.Ss[j][ty * 8 + 4];
            float4 v0 = *(const float4*)&s.Vs[j][tx * 8];
            float4 v1 = *(const float4*)&s.Vs[j][tx * 8 + 4];
            float pv[8] = {p0.x, p0.y, p0.z, p0.w, p1.x, p1.y, p1.z, p1.w};
            float vv[8] = {v0.x, v0.y, v0.z, v0.w, v1.x, v1.y, v1.z, v1.w};
#pragma unroll
            for (int i = 0; i < 8; i++)
#pragma unroll
                for (int jd = 0; jd < 8; jd++)
                    accO[i][jd] += pv[i] * vv[jd];
        }
        __syncthreads();
    }

    float linv[8];
#pragma unroll
    for (int i = 0; i < 8; i++) linv[i] = 1.f / s.l_sm[ty * 8 + i];
    float* Ob = O + ((size_t)(b * T_) * NH + h) * DK;
#pragma unroll
    for (int i = 0; i < 8; i++) {
        float4 o0 = make_float4(accO[i][0] * linv[i], accO[i][1] * linv[i],
                                accO[i][2] * linv[i], accO[i][3] * linv[i]);
        float4 o1 = make_float4(accO[i][4] * linv[i], accO[i][5] * linv[i],
                                accO[i][6] * linv[i], accO[i][7] * linv[i]);
        float* dst = Ob + (size_t)(q0 + ty * 8 + i) * qstride + tx * 8;
        *(float4*)(dst)     = o0;
        *(float4*)(dst + 4) = o1;
    }
}

// ---------------- launch --------------------------------------------------------
extern "C" void kernel_launch(void* const* d_in, const int* in_sizes, int n_in,
                              void* d_out, int out_size)
{
    const float* x  = (const float*)d_in[0];
    const float* wq = (const float*)d_in[1];
    const float* wk = (const float*)d_in[2];
    const float* wv = (const float*)d_in[3];
    const float* wo = (const float*)d_in[4];
    float* out = (float*)d_out;

    float *Qd, *Kd, *Vd, *Ad;
    cudaGetSymbolAddress((void**)&Qd, g_Q);
    cudaGetSymbolAddress((void**)&Kd, g_K);
    cudaGetSymbolAddress((void**)&Vd, g_V);
    cudaGetSymbolAddress((void**)&Ad, g_A);

    __nv_bfloat16 *xhi, *xlo, *ahi, *alo;
    __nv_bfloat16 *wqhi, *wqlo, *wkhi, *wklo, *wvhi, *wvlo, *wohi, *wolo;
    cudaGetSymbolAddress((void**)&xhi,  g_xhi);  cudaGetSymbolAddress((void**)&xlo,  g_xlo);
    cudaGetSymbolAddress((void**)&ahi,  g_ahi);  cudaGetSymbolAddress((void**)&alo,  g_alo);
    cudaGetSymbolAddress((void**)&wqhi, g_wqhi); cudaGetSymbolAddress((void**)&wqlo, g_wqlo);
    cudaGetSymbolAddress((void**)&wkhi, g_wkhi); cudaGetSymbolAddress((void**)&wklo, g_wklo);
    cudaGetSymbolAddress((void**)&wvhi, g_wvhi); cudaGetSymbolAddress((void**)&wvlo, g_wvlo);
    cudaGetSymbolAddress((void**)&wohi, g_wohi); cudaGetSymbolAddress((void**)&wolo, g_wolo);

    const int M = B_ * T_;       // 4096
    const int NX = 8388608;      // 4096*2048
    const int NW = 4194304;      // 2048*2048
    const int NKW = 1048576;     // 512*2048

    freq_init_kernel<<<1, 32>>>();

    cvt_split<<<NX / 1024, 256>>>(x,  xhi,  xlo,  NX);
    cvt_split<<<NW / 1024, 256>>>(wq, wqhi, wqlo, NW);
    cvt_split<<<NKW / 1024, 256>>>(wk, wkhi, wklo, NKW);
    cvt_split<<<NKW / 1024, 256>>>(wv, wvhi, wvlo, NKW);
    cvt_split<<<NW / 1024, 256>>>(wo, wohi, wolo, NW);

    cudaFuncSetAttribute(gemm_bf16x3,
                         cudaFuncAttributeMaxDynamicSharedMemorySize, GEMM_SMEM);

    gemm_bf16x3<<<dim3(DMODEL / 128, M / 128), 256, GEMM_SMEM>>>(
        xhi, xlo, wqhi, wqlo, Qd, DMODEL, DMODEL);
    gemm_bf16x3<<<dim3((NKV * DK) / 128, M / 128), 256, GEMM_SMEM>>>(
        xhi, xlo, wkhi, wklo, Kd, NKV * DK, DMODEL);
    gemm_bf16x3<<<dim3((NKV * DK) / 128, M / 128), 256, GEMM_SMEM>>>(
        xhi, xlo, wvhi, wvlo, Vd, NKV * DK, DMODEL);

    rope_kernel<<<(B_ * T_ * NH * 32 + 255) / 256, 256>>>(Qd, NH);
    rope_kernel<<<(B_ * T_ * NKV * 32 + 255) / 256, 256>>>(Kd, NKV);

    const int fsm = (int)sizeof(FlashSmem);
    cudaFuncSetAttribute(flash_kernel,
                         cudaFuncAttributeMaxDynamicSharedMemorySize, fsm);
    flash_kernel<<<dim3(T_ / FBM, B_ * NH), 256, fsm>>>(Qd, Kd, Vd, Ad);

    cvt_split<<<NX / 1024, 256>>>(Ad, ahi, alo, NX);
    gemm_bf16x3<<<dim3(DMODEL / 128, M / 128), 256, GEMM_SMEM>>>(
        ahi, alo, wohi, wolo, out, DMODEL, DMODEL);
}